// round 2
// baseline (speedup 1.0000x reference)
#include <cuda_runtime.h>
#include <cuda_bf16.h>

// Problem shapes (fixed by the dataset).
#define BATCH 4
#define NB    2048
#define NC    4
#define NWALL 64          // NB / 32
#define MAXI  1024        // cap for shared-memory adjacency bitmatrix path

// Scratch (no allocations allowed; __device__ globals are the sanctioned path).
__device__ int g_deg[BATCH * NB];            // neighbor count (excluding self), per batch
__device__ int g_order[BATCH * NC * NB];     // score-descending argsort per (b,c)

__device__ __forceinline__ float iou_val(float ax1, float ay1, float ax2, float ay2, float aar,
                                         float bx1, float by1, float bx2, float by2, float bar) {
    float ix = fminf(ax2, bx2) - fmaxf(ax1, bx1);
    float iy = fminf(ay2, by2) - fmaxf(ay1, by1);
    ix = fmaxf(ix, 0.0f);
    iy = fmaxf(iy, 0.0f);
    float inter = ix * iy;
    float uni = aar + bar - inter;
    return inter / fmaxf(uni, 1e-6f);   // matches reference: inter / max(union, 1e-6)
}

// ---------------------------------------------------------------------------
// Kernel 1: per-batch degree of the IoU>thr graph (self excluded).
// grid = BATCH * 64 blocks, 256 threads. Each warp handles 4 rows, lanes
// sweep 64 column-chunks of 32 from shared-staged boxes.
// ---------------------------------------------------------------------------
__global__ void __launch_bounds__(256) deg_kernel(const float* __restrict__ boxes,
                                                  const float* __restrict__ thrp) {
    __shared__ float sx1[NB], sy1[NB], sx2[NB], sy2[NB], sar[NB];
    int b    = blockIdx.x >> 6;
    int tile = blockIdx.x & 63;
    int tid  = threadIdx.x;
    const float* bb = boxes + (size_t)b * NB * 4;

    for (int i = tid; i < NB; i += 256) {
        float x1 = bb[i * 4 + 0], y1 = bb[i * 4 + 1];
        float x2 = bb[i * 4 + 2], y2 = bb[i * 4 + 3];
        sx1[i] = x1; sy1[i] = y1; sx2[i] = x2; sy2[i] = y2;
        sar[i] = (x2 - x1) * (y2 - y1);
    }
    __syncthreads();

    float thr = thrp[0];
    int warp = tid >> 5, lane = tid & 31;

    for (int rr = 0; rr < 4; rr++) {
        int r = tile * 32 + warp * 4 + rr;
        float ax1 = sx1[r], ay1 = sy1[r], ax2 = sx2[r], ay2 = sy2[r], aar = sar[r];
        int cnt = 0;
        #pragma unroll 4
        for (int c = 0; c < NWALL; c++) {
            int u = c * 32 + lane;
            float v = iou_val(ax1, ay1, ax2, ay2, aar,
                              sx1[u], sy1[u], sx2[u], sy2[u], sar[u]);
            cnt += (v > thr) ? 1 : 0;
        }
        int tot = __reduce_add_sync(0xffffffffu, cnt);
        if (lane == 0) g_deg[b * NB + r] = tot - 1;   // subtract self (IoU==1)
    }
}

// ---------------------------------------------------------------------------
// Kernel 2: bitonic argsort, descending by score, ties -> ascending index
// (matches stable jnp.argsort(-scores)). grid = 16, block = 1024.
// ---------------------------------------------------------------------------
__global__ void __launch_bounds__(1024) sort_kernel(const float* __restrict__ scores) {
    __shared__ float sk[NB];
    __shared__ int   si[NB];
    int bc  = blockIdx.x;
    int tid = threadIdx.x;
    const float* sp = scores + (size_t)bc * NB;

    for (int i = tid; i < NB; i += 1024) { sk[i] = sp[i]; si[i] = i; }
    __syncthreads();

    for (int k = 2; k <= NB; k <<= 1) {
        for (int j = k >> 1; j > 0; j >>= 1) {
            for (int i = tid; i < NB; i += 1024) {
                int l = i ^ j;
                if (l > i) {
                    float ki = sk[i], kl = sk[l];
                    int   ii = si[i], il = si[l];
                    // before(a,b): a goes earlier (higher score, or equal score + lower idx)
                    bool l_before_i = (kl > ki) || (kl == ki && il < ii);
                    bool i_before_l = (ki > kl) || (ki == kl && ii < il);
                    bool doswap = ((i & k) == 0) ? l_before_i : i_before_l;
                    if (doswap) { sk[i] = kl; sk[l] = ki; si[i] = il; si[l] = ii; }
                }
            }
            __syncthreads();
        }
    }
    for (int i = tid; i < NB; i += 1024) g_order[(size_t)bc * NB + i] = si[i];
}

// ---------------------------------------------------------------------------
// Kernel 3: per-(b,c) greedy NMS-match over the compacted "interesting" set
// (score > sthr AND degree > 0). grid = 16, block = 256, large dynamic smem.
// Output is FLOAT32 (harness __output__ dtype): match index or -1.0f.
// ---------------------------------------------------------------------------
// Dynamic shared layout (in 32-bit words):
//   adj       : MAXI * 32              (bitmatrix rows, 32 words each)
//   cx1..car  : 5 * NB                 (SoA compacted boxes + area)
//   cidx      : NB                     (compacted -> original index)
//   ords      : NB                     (order array staged)
//   chunkmask : 64, chunkoff : 64, sup : 64, sI : 16 (pad)
#define SMEM_WORDS (MAXI * 32 + 5 * NB + NB + NB + 64 + 64 + 64 + 16)
#define SMEM_BYTES (SMEM_WORDS * 4)

__global__ void __launch_bounds__(256) greedy_kernel(const float* __restrict__ boxes,
                                                     const float* __restrict__ scores,
                                                     const float* __restrict__ thrp,
                                                     const float* __restrict__ sthrp,
                                                     float* __restrict__ out) {
    extern __shared__ unsigned smem[];
    unsigned* adj       = smem;
    float*    cx1       = (float*)(adj + MAXI * 32);
    float*    cy1       = cx1 + NB;
    float*    cx2       = cy1 + NB;
    float*    cy2       = cx2 + NB;
    float*    car       = cy2 + NB;
    int*      cidx      = (int*)(car + NB);
    int*      ords      = cidx + NB;
    unsigned* chunkmask = (unsigned*)(ords + NB);
    int*      chunkoff  = (int*)(chunkmask + 64);
    unsigned* sup       = (unsigned*)(chunkoff + 64);
    int*      sIp       = (int*)(sup + 64);

    int bc   = blockIdx.x;
    int b    = bc / NC;
    int tid  = threadIdx.x;
    int lane = tid & 31;
    int warp = tid >> 5;

    float thr  = thrp[0];
    float sthr = sthrp[0];
    const float* sp = scores + (size_t)bc * NB;
    const float* bb = boxes + (size_t)b * NB * 4;
    float* op = out + (size_t)bc * NB;

    // Output init: degree-0 active boxes are always their own leaders;
    // inactive boxes are never matched (-1). Interesting boxes get
    // overwritten by the greedy phase when claimed.
    for (int n = tid; n < NB; n += 256)
        op[n] = (sp[n] > sthr) ? (float)n : -1.0f;

    // Phase 1: flags in score order + per-chunk ballots.
    for (int r = 0; r < NB / 256; r++) {
        int i = tid + 256 * r;                      // warp w covers chunk 8r+w, bit = lane
        int t = g_order[(size_t)bc * NB + i];
        ords[i] = t;
        bool f = (g_deg[b * NB + t] > 0) && (sp[t] > sthr);
        unsigned bal = __ballot_sync(0xffffffffu, f);
        if (lane == 0) chunkmask[i >> 5] = bal;
    }
    __syncthreads();

    // Phase 2: exclusive prefix over 64 chunk counts.
    if (tid == 0) {
        int acc = 0;
        for (int c = 0; c < NWALL; c++) { chunkoff[c] = acc; acc += __popc(chunkmask[c]); }
        sIp[0] = acc;
    }
    __syncthreads();
    int I = sIp[0];

    // Phase 3: compact interesting boxes (kept in score order) into SoA.
    for (int r = 0; r < NB / 256; r++) {
        int ch = 8 * r + warp;
        unsigned mask = chunkmask[ch];
        if ((mask >> lane) & 1u) {
            int pos = chunkoff[ch] + __popc(mask & ((1u << lane) - 1u));
            int t = ords[ch * 32 + lane];
            cidx[pos] = t;
            float x1 = bb[t * 4 + 0], y1 = bb[t * 4 + 1];
            float x2 = bb[t * 4 + 2], y2 = bb[t * 4 + 3];
            cx1[pos] = x1; cy1[pos] = y1; cx2[pos] = x2; cy2[pos] = y2;
            car[pos] = (x2 - x1) * (y2 - y1);
        }
    }
    __syncthreads();

    int nwI = (I + 31) >> 5;

    // Phase 4: adjacency bitmatrix among compacted boxes (main path only).
    if (I <= MAXI) {
        for (int rr = warp; rr < I; rr += 8) {
            float ax1 = cx1[rr], ay1 = cy1[rr], ax2 = cx2[rr], ay2 = cy2[rr], aar = car[rr];
            for (int w = 0; w < nwI; w++) {
                int u = w * 32 + lane;
                bool hit = false;
                if (u < I) {
                    float v = iou_val(ax1, ay1, ax2, ay2, aar,
                                      cx1[u], cy1[u], cx2[u], cy2[u], car[u]);
                    hit = v > thr;
                }
                unsigned word = __ballot_sync(0xffffffffu, hit);
                if (lane == 0) adj[rr * 32 + w] = word;
            }
        }
    }
    __syncthreads();

    // Phase 5: exact sequential greedy over the interesting set (warp 0 only).
    if (warp == 0) {
        sup[lane] = 0u;
        sup[lane + 32] = 0u;
        __syncwarp();

        if (I <= MAXI) {
            for (int i = 0; i < I; i++) {
                if ((sup[i >> 5] >> (i & 31)) & 1u) continue;   // already grouped
                float leader = (float)cidx[i];
                unsigned m = 0u;
                if (lane < nwI) {
                    m = adj[i * 32 + lane] & ~sup[lane];         // claims vs pre-state
                    sup[lane] |= m;
                }
                int base = lane << 5;
                while (m) {
                    int b2 = __ffs(m) - 1;
                    m &= m - 1u;
                    op[cidx[base + b2]] = leader;
                }
                __syncwarp();
            }
        } else {
            // Fallback: on-the-fly IoU rows (correct for any I up to NB).
            for (int i = 0; i < I; i++) {
                if ((sup[i >> 5] >> (i & 31)) & 1u) continue;
                float leader = (float)cidx[i];
                float ax1 = cx1[i], ay1 = cy1[i], ax2 = cx2[i], ay2 = cy2[i], aar = car[i];
                for (int w = 0; w < nwI; w++) {
                    int u = w * 32 + lane;
                    bool hit = false;
                    if (u < I && !((sup[w] >> lane) & 1u)) {
                        float v = iou_val(ax1, ay1, ax2, ay2, aar,
                                          cx1[u], cy1[u], cx2[u], cy2[u], car[u]);
                        hit = v > thr;
                    }
                    unsigned word = __ballot_sync(0xffffffffu, hit);
                    if (hit) op[cidx[u]] = leader;
                    if (lane == 0) sup[w] |= word;
                }
                __syncwarp();
            }
        }
    }
}

// ---------------------------------------------------------------------------
// Launch
// ---------------------------------------------------------------------------
extern "C" void kernel_launch(void* const* d_in, const int* in_sizes, int n_in,
                              void* d_out, int out_size) {
    const float* boxes  = (const float*)d_in[0];
    const float* scores = (const float*)d_in[1];
    const float* iouthr = (const float*)d_in[2];
    const float* scothr = (const float*)d_in[3];
    float* out = (float*)d_out;

    cudaFuncSetAttribute(greedy_kernel,
                         cudaFuncAttributeMaxDynamicSharedMemorySize, SMEM_BYTES);

    deg_kernel<<<BATCH * 64, 256>>>(boxes, iouthr);
    sort_kernel<<<BATCH * NC, 1024>>>(scores);
    greedy_kernel<<<BATCH * NC, 256, SMEM_BYTES>>>(boxes, scores, iouthr, scothr, out);
}

// round 3
// speedup vs baseline: 2.9367x; 2.9367x over previous
#include <cuda_runtime.h>
#include <cuda_bf16.h>

#define BATCH  4
#define NB     2048
#define NC     4
#define MAXDEG 64          // global adjacency slots per row
#define ADJ_S  8           // smem-cached neighbors per interesting candidate

// __device__ globals (no allocations allowed). g_adj aligned for uint4 copies.
__device__ uint4 g_adj_raw[(size_t)BATCH * NB * MAXDEG / 8];
#define G_ADJ ((unsigned short*)g_adj_raw)
__device__ int g_deg[BATCH * NB];
__device__ int g_order[BATCH * NC * NB];

// ---------------------------------------------------------------------------
// Kernel A (fused): blocks [0, BATCH*128) build adjacency lists + degree;
// last BATCH*NC blocks do score-descending argsort (stable by index).
// ---------------------------------------------------------------------------
__global__ void __launch_bounds__(512) prep_kernel(const float4* __restrict__ boxes,
                                                   const float* __restrict__ scores,
                                                   const float* __restrict__ thrp) {
    extern __shared__ unsigned char dynsmem[];
    int tid = threadIdx.x;

    if (blockIdx.x < BATCH * 128) {
        // ----- adjacency build: 16 rows per block, one row per warp -----
        float4* sbox = (float4*)dynsmem;            // 2048 * 16B = 32KB
        int b    = blockIdx.x >> 7;
        int tile = blockIdx.x & 127;
        const float4* bb = boxes + (size_t)b * NB;
        for (int i = tid; i < NB; i += 512) sbox[i] = bb[i];
        __syncthreads();

        float thr = thrp[0];
        int warp = tid >> 5, lane = tid & 31;
        int r = tile * 16 + warp;

        float4 rb = sbox[r];
        float rar = (rb.z - rb.x) * (rb.w - rb.y);
        int cnt = 0;
        unsigned short* row = G_ADJ + (size_t)(b * NB + r) * MAXDEG;

        #pragma unroll 4
        for (int c = 0; c < NB / 32; c++) {
            int u = c * 32 + lane;
            float4 ub = sbox[u];
            float uar = (ub.z - ub.x) * (ub.w - ub.y);
            float ix = fminf(rb.z, ub.z) - fmaxf(rb.x, ub.x);
            float iy = fminf(rb.w, ub.w) - fmaxf(rb.y, ub.y);
            ix = fmaxf(ix, 0.0f);
            iy = fmaxf(iy, 0.0f);
            float inter = ix * iy;
            float unim  = fmaxf(rar + uar - inter, 1e-6f);
            bool hit = inter > thr * unim;          // == inter/max(uni,1e-6) > thr
            unsigned word = __ballot_sync(0xffffffffu, hit);
            if (c == (r >> 5)) word &= ~(1u << (r & 31));   // drop self
            if (lane == 0 && word) {
                int base = c * 32;
                while (word) {
                    int j = __ffs(word) - 1;
                    word &= word - 1u;
                    if (cnt < MAXDEG) row[cnt] = (unsigned short)(base + j);
                    cnt++;                           // full count even if truncated
                }
            }
        }
        if (lane == 0) g_deg[b * NB + r] = cnt;
    } else {
        // ----- bitonic argsort for one (b,c): descending score, ties by index -----
        float* sk = (float*)dynsmem;                 // 8KB
        int*   si = (int*)(dynsmem + NB * 4);        // 8KB
        int bc = blockIdx.x - BATCH * 128;
        const float* sp = scores + (size_t)bc * NB;
        for (int i = tid; i < NB; i += 512) { sk[i] = sp[i]; si[i] = i; }
        __syncthreads();
        for (int k = 2; k <= NB; k <<= 1) {
            for (int j = k >> 1; j > 0; j >>= 1) {
                for (int i = tid; i < NB; i += 512) {
                    int l = i ^ j;
                    if (l > i) {
                        float ki = sk[i], kl = sk[l];
                        int   ii = si[i], il = si[l];
                        bool lbi = (kl > ki) || (kl == ki && il < ii);
                        bool ibl = (ki > kl) || (ki == kl && ii < il);
                        bool sw = ((i & k) == 0) ? lbi : ibl;
                        if (sw) { sk[i] = kl; sk[l] = ki; si[i] = il; si[l] = ii; }
                    }
                }
                __syncthreads();
            }
        }
        for (int i = tid; i < NB; i += 512) g_order[(size_t)bc * NB + i] = si[i];
    }
}

// ---------------------------------------------------------------------------
// Kernel B: per-(b,c) greedy NMS-match via adjacency lists. grid=16, 256 thr.
// ---------------------------------------------------------------------------
// smem byte offsets
#define OFF_SUP   0                      // 2048 x u8
#define OFF_CIDX  2048                   // 2048 x int
#define OFF_CDEG  (OFF_CIDX + 8192)      // 2048 x int
#define OFF_ORDS  (OFF_CDEG + 8192)      // 2048 x int
#define OFF_CMSK  (OFF_ORDS + 8192)      // 64 x u32
#define OFF_COFF  (OFF_CMSK + 256)       // 65 x int
#define OFF_ADJS  (OFF_COFF + 272)       // 2048 x 8 x u16 (16B aligned)
#define OFF_CBOX  (OFF_ADJS + 32768)     // 2048 x float4 (16B aligned)
#define SMEM_B    (OFF_CBOX + 32768)

__global__ void __launch_bounds__(256) greedy_kernel(const float4* __restrict__ boxes,
                                                     const float* __restrict__ scores,
                                                     const float* __restrict__ thrp,
                                                     const float* __restrict__ sthrp,
                                                     float* __restrict__ out) {
    extern __shared__ unsigned char sm[];
    unsigned char*          sup8  = sm + OFF_SUP;
    volatile unsigned char* sup8v = sm + OFF_SUP;
    int*            candIdx  = (int*)(sm + OFF_CIDX);
    int*            candDeg  = (int*)(sm + OFF_CDEG);
    int*            ords     = (int*)(sm + OFF_ORDS);
    unsigned*       chunkmsk = (unsigned*)(sm + OFF_CMSK);
    int*            chunkoff = (int*)(sm + OFF_COFF);
    unsigned short* adjS     = (unsigned short*)(sm + OFF_ADJS);
    float4*         cbox     = (float4*)(sm + OFF_CBOX);

    int bc = blockIdx.x;
    int b  = bc / NC;
    int tid = threadIdx.x, lane = tid & 31, warp = tid >> 5;

    float thr  = thrp[0];
    float sthr = sthrp[0];
    const float*  sp = scores + (size_t)bc * NB;
    const float4* bb = boxes + (size_t)b * NB;
    float* op = out + (size_t)bc * NB;

    // P1: output init + score-suppression mask.
    for (int n = tid; n < NB; n += 256) {
        bool act = sp[n] > sthr;
        op[n]   = act ? (float)n : -1.0f;
        sup8[n] = act ? 0 : 1;
    }
    __syncthreads();

    // P2: flags in score order, per-32-chunk ballots.
    for (int rr = 0; rr < NB / 256; rr++) {
        int i = tid + 256 * rr;
        int t = g_order[(size_t)bc * NB + i];
        ords[i] = t;
        bool f = (sup8[t] == 0) && (g_deg[b * NB + t] > 0);
        unsigned bal = __ballot_sync(0xffffffffu, f);
        if (lane == 0) chunkmsk[i >> 5] = bal;
    }
    __syncthreads();

    // P3: exclusive prefix over 64 chunk popcounts.
    if (tid == 0) {
        int acc = 0;
        for (int c = 0; c < 64; c++) { chunkoff[c] = acc; acc += __popc(chunkmsk[c]); }
        chunkoff[64] = acc;
    }
    __syncthreads();
    int I = chunkoff[64];

    // P4: scatter interesting candidates (score order preserved):
    //     index, degree, coords, and first 8 adjacency entries (one uint4).
    for (int rr = 0; rr < NB / 256; rr++) {
        int ch = 8 * rr + warp;
        unsigned mask = chunkmsk[ch];
        if ((mask >> lane) & 1u) {
            int pos = chunkoff[ch] + __popc(mask & ((1u << lane) - 1u));
            int t = ords[ch * 32 + lane];
            candIdx[pos] = t;
            candDeg[pos] = g_deg[b * NB + t];
            cbox[pos] = bb[t];
            uint4 a = *(const uint4*)(G_ADJ + (size_t)(b * NB + t) * MAXDEG);
            *(uint4*)(adjS + pos * ADJ_S) = a;
        }
    }
    __syncthreads();

    // P5: serial greedy (warp 0): chunked ballots over candidates; claims O(deg).
    if (warp == 0) {
        int nch = (I + 31) >> 5;
        for (int ch = 0; ch < nch; ch++) {
            int p0 = ch * 32;
            int p  = p0 + lane;
            bool cand = false;
            if (p < I) cand = (sup8v[candIdx[p]] == 0);
            unsigned ball = __ballot_sync(0xffffffffu, cand);
            while (ball) {
                int j = __ffs(ball) - 1;
                ball &= ball - 1u;
                int pj = p0 + j;
                int tj = candIdx[pj];               // broadcast LDS
                if (sup8v[tj]) continue;            // suppressed earlier in this chunk
                int d = candDeg[pj];
                if (lane == 0) sup8v[tj] = 1;       // op[tj] already == tj
                float leaderf = (float)tj;
                if (d <= MAXDEG) {
                    for (int base = 0; base < d; base += 32) {
                        int k = base + lane;
                        if (k < d) {
                            int u = (k < ADJ_S)
                                  ? (int)adjS[pj * ADJ_S + k]
                                  : (int)G_ADJ[(size_t)(b * NB + tj) * MAXDEG + k];
                            if (!sup8v[u]) { sup8v[u] = 1; op[u] = leaderf; }
                        }
                    }
                } else {
                    // rare/adversarial: list truncated -> exact sweep over
                    // interesting coords (any claimable box is interesting).
                    float4 tb = cbox[pj];
                    float tar = (tb.z - tb.x) * (tb.w - tb.y);
                    for (int base = 0; base < I; base += 32) {
                        int q = base + lane;
                        if (q < I) {
                            int u = candIdx[q];
                            if (!sup8v[u]) {
                                float4 ub = cbox[q];
                                float uar = (ub.z - ub.x) * (ub.w - ub.y);
                                float ix = fminf(tb.z, ub.z) - fmaxf(tb.x, ub.x);
                                float iy = fminf(tb.w, ub.w) - fmaxf(tb.y, ub.y);
                                ix = fmaxf(ix, 0.0f);
                                iy = fmaxf(iy, 0.0f);
                                float inter = ix * iy;
                                float unim  = fmaxf(tar + uar - inter, 1e-6f);
                                if (inter > thr * unim) { sup8v[u] = 1; op[u] = leaderf; }
                            }
                        }
                    }
                }
                __syncwarp();
            }
        }
    }
}

// ---------------------------------------------------------------------------
// Launch: two kernels (adjacency+sort fused, then greedy).
// ---------------------------------------------------------------------------
extern "C" void kernel_launch(void* const* d_in, const int* in_sizes, int n_in,
                              void* d_out, int out_size) {
    const float4* boxes  = (const float4*)d_in[0];
    const float*  scores = (const float*)d_in[1];
    const float*  iouthr = (const float*)d_in[2];
    const float*  scothr = (const float*)d_in[3];
    float* out = (float*)d_out;

    cudaFuncSetAttribute(greedy_kernel,
                         cudaFuncAttributeMaxDynamicSharedMemorySize, SMEM_B);

    prep_kernel<<<BATCH * 128 + BATCH * NC, 512, 32768>>>(boxes, scores, iouthr);
    greedy_kernel<<<BATCH * NC, 256, SMEM_B>>>(boxes, scores, iouthr, scothr, out);
}

// round 4
// speedup vs baseline: 3.6005x; 1.2260x over previous
#include <cuda_runtime.h>
#include <cuda_bf16.h>

#define BATCH  4
#define NB     2048
#define NC     4
#define MAXDEG 64          // adjacency slots per row
#define CAP    96          // max component size for per-thread path

// __device__ scratch (allocation-free rule).
__device__ unsigned short g_adj[(size_t)BATCH * NB * MAXDEG];
__device__ int            g_deg[BATCH * NB];          // FULL degree (may exceed MAXDEG)
__device__ unsigned short g_rank[BATCH * NC * NB];    // rank[t] = position in score-desc order

// ---------------------------------------------------------------------------
// K1 (fused): blocks [0, BATCH*128) adjacency lists + degree;
// last BATCH*NC blocks: bitonic argsort -> rank (stable: score desc, idx asc).
// ---------------------------------------------------------------------------
__global__ void __launch_bounds__(512) prep_kernel(const float4* __restrict__ boxes,
                                                   const float* __restrict__ scores,
                                                   const float* __restrict__ thrp) {
    extern __shared__ unsigned char dynsmem[];
    int tid = threadIdx.x;

    if (blockIdx.x < BATCH * 128) {
        float4* sbox = (float4*)dynsmem;                 // 32KB
        int b    = blockIdx.x >> 7;
        int tile = blockIdx.x & 127;
        const float4* bb = boxes + (size_t)b * NB;
        for (int i = tid; i < NB; i += 512) sbox[i] = bb[i];
        __syncthreads();

        float thr = thrp[0];
        int warp = tid >> 5, lane = tid & 31;
        int r = tile * 16 + warp;

        float4 rb = sbox[r];
        float rar = (rb.z - rb.x) * (rb.w - rb.y);
        int cnt = 0;
        unsigned short* row = g_adj + (size_t)(b * NB + r) * MAXDEG;

        #pragma unroll 4
        for (int c = 0; c < NB / 32; c++) {
            int u = c * 32 + lane;
            float4 ub = sbox[u];
            float uar = (ub.z - ub.x) * (ub.w - ub.y);
            float ix = fminf(rb.z, ub.z) - fmaxf(rb.x, ub.x);
            float iy = fminf(rb.w, ub.w) - fmaxf(rb.y, ub.y);
            ix = fmaxf(ix, 0.0f);
            iy = fmaxf(iy, 0.0f);
            float inter = ix * iy;
            float unim  = fmaxf(rar + uar - inter, 1e-6f);
            bool hit = inter > thr * unim;               // == inter/max(uni,1e-6) > thr
            unsigned word = __ballot_sync(0xffffffffu, hit);
            if (c == (r >> 5)) word &= ~(1u << (r & 31));     // drop self
            if (lane == 0 && word) {
                int base = c * 32;
                while (word) {
                    int j = __ffs(word) - 1;
                    word &= word - 1u;
                    if (cnt < MAXDEG) row[cnt] = (unsigned short)(base + j);
                    cnt++;                               // full count even if truncated
                }
            }
        }
        if (lane == 0) g_deg[b * NB + r] = cnt;
    } else {
        float* sk = (float*)dynsmem;
        int*   si = (int*)(dynsmem + NB * 4);
        int bc = blockIdx.x - BATCH * 128;
        const float* sp = scores + (size_t)bc * NB;
        for (int i = tid; i < NB; i += 512) { sk[i] = sp[i]; si[i] = i; }
        __syncthreads();
        for (int k = 2; k <= NB; k <<= 1) {
            for (int j = k >> 1; j > 0; j >>= 1) {
                for (int i = tid; i < NB; i += 512) {
                    int l = i ^ j;
                    if (l > i) {
                        float ki = sk[i], kl = sk[l];
                        int   ii = si[i], il = si[l];
                        bool lbi = (kl > ki) || (kl == ki && il < ii);
                        bool ibl = (ki > kl) || (ki == kl && ii < il);
                        bool sw = ((i & k) == 0) ? lbi : ibl;
                        if (sw) { sk[i] = kl; sk[l] = ki; si[i] = il; si[l] = ii; }
                    }
                }
                __syncthreads();
            }
        }
        for (int i = tid; i < NB; i += 512)
            g_rank[(size_t)bc * NB + si[i]] = (unsigned short)i;   // inverse perm
    }
}

// ---------------------------------------------------------------------------
// K2: connected-component parallel greedy. 1 block per batch, 1024 threads.
// Thread i BFS-walks its component (aborts unless i is the component min),
// then runs the exact greedy locally for all 4 classes. Components are
// disjoint -> no synchronization. Fallback (exact serial) if deg>MAXDEG or
// component>CAP anywhere in the batch (deterministic, data-dependent).
// ---------------------------------------------------------------------------
// smem byte offsets
#define SM_SUP   0                       // 4*2048 u8
#define SM_RANK  8192                    // 4*2048 u16
#define SM_ORDS  24576                   // 4*2048 u16 (fallback only)
#define SM_BOX   40960                   // 2048 float4 (fallback only)
#define SM_FLAG  73728                   // int
#define SMEM_K2  73744

__global__ void __launch_bounds__(1024) cc_greedy_kernel(const float4* __restrict__ boxes,
                                                         const float* __restrict__ scores,
                                                         const float* __restrict__ thrp,
                                                         const float* __restrict__ sthrp,
                                                         float* __restrict__ out) {
    extern __shared__ unsigned char sm[];
    unsigned char*  sup  = sm + SM_SUP;
    unsigned short* rnk  = (unsigned short*)(sm + SM_RANK);
    unsigned short* ords = (unsigned short*)(sm + SM_ORDS);
    float4*         sbox = (float4*)(sm + SM_BOX);
    int*            sflag = (int*)(sm + SM_FLAG);

    int b = blockIdx.x;
    int tid = threadIdx.x;
    if (tid == 0) *sflag = 0;
    float sthr = sthrp[0];

    // P1: per-class active mask + output init + rank staging.
    for (int idx = tid; idx < NC * NB; idx += 1024) {
        int c = idx >> 11, n = idx & (NB - 1);
        size_t g = (size_t)(b * NC + c) * NB + n;
        bool act = scores[g] > sthr;
        sup[idx] = act ? 0 : 1;
        out[g]   = act ? (float)n : -1.0f;
        rnk[idx] = g_rank[g];
    }
    __syncthreads();

    // P2: per-component greedy.
    for (int i = tid; i < NB; i += 1024) {
        int d = g_deg[b * NB + i];
        if (d <= 0) continue;                 // isolated: init already correct
        if (d > MAXDEG) { *sflag = 1; continue; }

        unsigned short memb[CAP];
        int mc = 1; memb[0] = (unsigned short)i;
        bool root = true, ovf = false;
        for (int h = 0; h < mc && root && !ovf; h++) {
            int v = memb[h];
            int dv = g_deg[b * NB + v];
            if (dv > MAXDEG) { ovf = true; break; }
            const unsigned short* row = g_adj + (size_t)(b * NB + v) * MAXDEG;
            for (int e = 0; e < dv; e++) {
                int u = row[e];
                if (u < i) { root = false; break; }       // not the component min
                bool seen = false;
                for (int j = 0; j < mc; j++) if (memb[j] == u) { seen = true; break; }
                if (!seen) {
                    if (mc == CAP) { ovf = true; break; }
                    memb[mc++] = (unsigned short)u;
                }
            }
        }
        if (ovf) { *sflag = 1; continue; }
        if (!root) continue;

        for (int c = 0; c < NC; c++) {
            unsigned char* supc = sup + (c << 11);
            const unsigned short* rc = rnk + (c << 11);
            float* opc = out + (size_t)(b * NC + c) * NB;
            while (true) {
                int best = -1, br = 1 << 20;
                for (int j = 0; j < mc; j++) {
                    int m = memb[j];
                    if (supc[m] == 0) { int r = rc[m]; if (r < br) { br = r; best = m; } }
                }
                if (best < 0) break;
                supc[best] = 1;                            // opc[best] already == best
                int dv = g_deg[b * NB + best];
                const unsigned short* row = g_adj + (size_t)(b * NB + best) * MAXDEG;
                float lf = (float)best;
                for (int e = 0; e < dv; e++) {
                    int u = row[e];
                    if (supc[u] == 0) { supc[u] = 1; opc[u] = lf; }
                }
            }
        }
    }
    __syncthreads();

    // P3: exact serial fallback (adversarial inputs only; rewrites everything).
    if (*sflag) {
        float thr = thrp[0];
        const float4* bb = boxes + (size_t)b * NB;
        for (int i = tid; i < NB; i += 1024) sbox[i] = bb[i];
        for (int idx = tid; idx < NC * NB; idx += 1024) {
            int c = idx >> 11, n = idx & (NB - 1);
            size_t g = (size_t)(b * NC + c) * NB + n;
            ords[(c << 11) + rnk[idx]] = (unsigned short)n;
            bool act = scores[g] > sthr;
            sup[idx] = act ? 0 : 1;
            out[g]   = act ? (float)n : -1.0f;
        }
        __syncthreads();
        int warp = tid >> 5, lane = tid & 31;
        if (warp < NC) {
            int c = warp;
            volatile unsigned char* supc = sup + (c << 11);
            float* opc = out + (size_t)(b * NC + c) * NB;
            for (int r = 0; r < NB; r++) {
                __syncwarp();
                int t = ords[(c << 11) + r];
                if (supc[t]) continue;
                float4 tb = sbox[t];
                float tar = (tb.z - tb.x) * (tb.w - tb.y);
                float lf = (float)t;
                for (int ch = 0; ch < NB / 32; ch++) {
                    int u = ch * 32 + lane;
                    if (supc[u] == 0) {
                        float4 ub = sbox[u];
                        float uar = (ub.z - ub.x) * (ub.w - ub.y);
                        float ix = fminf(tb.z, ub.z) - fmaxf(tb.x, ub.x);
                        float iy = fminf(tb.w, ub.w) - fmaxf(tb.y, ub.y);
                        ix = fmaxf(ix, 0.0f);
                        iy = fmaxf(iy, 0.0f);
                        float inter = ix * iy;
                        float unim  = fmaxf(tar + uar - inter, 1e-6f);
                        if (inter > thr * unim) { supc[u] = 1; opc[u] = lf; }
                    }
                }
            }
        }
    }
}

// ---------------------------------------------------------------------------
extern "C" void kernel_launch(void* const* d_in, const int* in_sizes, int n_in,
                              void* d_out, int out_size) {
    const float4* boxes  = (const float4*)d_in[0];
    const float*  scores = (const float*)d_in[1];
    const float*  iouthr = (const float*)d_in[2];
    const float*  scothr = (const float*)d_in[3];
    float* out = (float*)d_out;

    cudaFuncSetAttribute(cc_greedy_kernel,
                         cudaFuncAttributeMaxDynamicSharedMemorySize, SMEM_K2);

    prep_kernel<<<BATCH * 128 + BATCH * NC, 512, 32768>>>(boxes, scores, iouthr);
    cc_greedy_kernel<<<BATCH, 1024, SMEM_K2>>>(boxes, scores, iouthr, scothr, out);
}

// round 6
// speedup vs baseline: 4.7722x; 1.3254x over previous
#include <cuda_runtime.h>
#include <cuda_bf16.h>

#define BATCH  4
#define NB     2048
#define NC     4
#define MAXDEG 64          // adjacency slots per row
#define CAP    96          // max component size for per-thread greedy

// __device__ scratch (allocation-free rule).
__device__ unsigned short g_adj[(size_t)BATCH * NB * MAXDEG];
__device__ int            g_deg[BATCH * NB];
__device__ int            g_flag[BATCH];

// ---------------------------------------------------------------------------
// K1: adjacency lists + degree. 512 blocks x 512 thr, 16 rows/block.
// Also resets g_flag (block 0). No sort anymore.
// ---------------------------------------------------------------------------
__global__ void __launch_bounds__(512) adj_kernel(const float4* __restrict__ boxes,
                                                  const float* __restrict__ thrp) {
    __shared__ float4 sbox[NB];     // 32KB
    __shared__ float  sar[NB];      // 8KB
    int b    = blockIdx.x >> 7;
    int tile = blockIdx.x & 127;
    int tid  = threadIdx.x;
    if (blockIdx.x == 0 && tid < BATCH) g_flag[tid] = 0;

    const float4* bb = boxes + (size_t)b * NB;
    for (int i = tid; i < NB; i += 512) {
        float4 v = bb[i];
        sbox[i] = v;
        sar[i] = (v.z - v.x) * (v.w - v.y);
    }
    __syncthreads();

    float thr = thrp[0];
    int warp = tid >> 5, lane = tid & 31;
    int r = tile * 16 + warp;

    float4 rb = sbox[r];
    float rar = sar[r];
    int cnt = 0;
    unsigned short* row = g_adj + (size_t)(b * NB + r) * MAXDEG;

    #pragma unroll 4
    for (int c = 0; c < NB / 32; c++) {
        int u = c * 32 + lane;
        float4 ub = sbox[u];
        float ix = fminf(rb.z, ub.z) - fmaxf(rb.x, ub.x);
        float iy = fminf(rb.w, ub.w) - fmaxf(rb.y, ub.y);
        ix = fmaxf(ix, 0.0f);
        iy = fmaxf(iy, 0.0f);
        float inter = ix * iy;
        float unim  = fmaxf(rar + sar[u] - inter, 1e-6f);
        bool hit = inter > thr * unim;               // == inter/max(uni,1e-6) > thr
        unsigned word = __ballot_sync(0xffffffffu, hit);
        if (c == (r >> 5)) word &= ~(1u << (r & 31));     // drop self
        if (lane == 0 && word) {
            int base = c * 32;
            while (word) {
                int j = __ffs(word) - 1;
                word &= word - 1u;
                if (cnt < MAXDEG) row[cnt] = (unsigned short)(base + j);
                cnt++;                                // full count even if truncated
            }
        }
    }
    if (lane == 0) g_deg[b * NB + r] = cnt;
}

// ---------------------------------------------------------------------------
// K2: per-thread component greedy. grid = BATCH*8, 256 thr. Thread owns node
// i; if isolated, writes its own outputs. Else BFS (smem bitmap dedup); only
// the component-min thread proceeds as root and writes ALL member outputs for
// all 4 classes. Disjoint components -> race-free. Overflow -> g_flag[b].
// Assumes thr < 1 (self-IoU=1 > thr => active boxes self-match). Dataset: 0.5.
// ---------------------------------------------------------------------------
#define SEEN_WORDS 64      // 2048 bits
#define K2_SMEM (SEEN_WORDS * 256 * 4)   // 64KB, interleaved [w*256 + tid]

__global__ void __launch_bounds__(256) cc_kernel(const float* __restrict__ scores,
                                                 const float* __restrict__ sthrp,
                                                 float* __restrict__ out) {
    extern __shared__ unsigned seenS[];
    int b   = blockIdx.x >> 3;
    int tid = threadIdx.x;
    int i   = (blockIdx.x & 7) * 256 + tid;
    float sthr = sthrp[0];

    int d = g_deg[b * NB + i];
    if (d == 0) {
        #pragma unroll
        for (int c = 0; c < NC; c++) {
            size_t g = (size_t)(b * NC + c) * NB + i;
            out[g] = (scores[g] > sthr) ? (float)i : -1.0f;
        }
        return;
    }
    if (d > MAXDEG) { g_flag[b] = 1; return; }

    // BFS with O(1) dedup (conflict-free smem bitmap).
    #pragma unroll
    for (int w = 0; w < SEEN_WORDS; w++) seenS[w * 256 + tid] = 0u;
    seenS[(i >> 5) * 256 + tid] = 1u << (i & 31);

    unsigned short memb[CAP];
    memb[0] = (unsigned short)i;
    int mc = 1;
    bool root = true, ovf = false;

    for (int h = 0; h < mc; h++) {
        int v = memb[h];
        int dv = (h == 0) ? d : g_deg[b * NB + v];
        if (dv > MAXDEG) { ovf = true; break; }
        const unsigned short* row = g_adj + (size_t)(b * NB + v) * MAXDEG;
        for (int e = 0; e < dv; e++) {
            int u = row[e];
            if (u < i) { root = false; break; }       // not the component min
            unsigned m = 1u << (u & 31);
            unsigned* sw = &seenS[(u >> 5) * 256 + tid];
            if (!(*sw & m)) {
                *sw |= m;
                if (mc == CAP) { ovf = true; break; }
                memb[mc++] = (unsigned short)u;
            }
        }
        if (!root || ovf) break;
    }
    if (ovf) { g_flag[b] = 1; return; }
    if (!root) return;

    // Exact greedy per class, fully local (max score, tie -> min index).
    float sc[CAP];
    for (int c = 0; c < NC; c++) {
        const float* spc = scores + (size_t)(b * NC + c) * NB;
        float*       opc = out + (size_t)(b * NC + c) * NB;
        unsigned act[3] = {0u, 0u, 0u};               // unclaimed-active members
        int nact = 0;
        for (int j = 0; j < mc; j++) {
            float s = spc[memb[j]];
            sc[j] = s;
            if (s > sthr) { act[j >> 5] |= 1u << (j & 31); nact++; }
            else opc[memb[j]] = -1.0f;
        }
        while (nact > 0) {
            int bj = -1, bidx = 1 << 30;
            float bs = -1e30f;
            for (int j = 0; j < mc; j++) {
                if ((act[j >> 5] >> (j & 31)) & 1u) {
                    float s = sc[j];
                    int g = memb[j];
                    if (s > bs || (s == bs && g < bidx)) { bs = s; bj = j; bidx = g; }
                }
            }
            act[bj >> 5] &= ~(1u << (bj & 31));
            nact--;
            opc[bidx] = (float)bidx;                   // self-claim (thr < 1)
            int dv = g_deg[b * NB + bidx];
            const unsigned short* row = g_adj + (size_t)(b * NB + bidx) * MAXDEG;
            for (int e = 0; e < dv; e++) {
                int u = row[e];
                for (int j = 0; j < mc; j++) {         // slot lookup (mc small)
                    if (memb[j] == u) {
                        if ((act[j >> 5] >> (j & 31)) & 1u) {
                            act[j >> 5] &= ~(1u << (j & 31));
                            nact--;
                            opc[u] = (float)bidx;
                        }
                        break;
                    }
                }
            }
        }
    }
}

// ---------------------------------------------------------------------------
// K3: exact serial fallback per batch; early-exits unless g_flag[b] set.
// ---------------------------------------------------------------------------
#define K3_SBOX 0                       // 2048 float4
#define K3_SAR  32768                   // 2048 float
#define K3_SUP  40960                   // NC*2048 u8
#define K3_SMEM (K3_SUP + NC * NB)

__global__ void __launch_bounds__(1024) fb_kernel(const float4* __restrict__ boxes,
                                                  const float* __restrict__ scores,
                                                  const float* __restrict__ thrp,
                                                  const float* __restrict__ sthrp,
                                                  float* __restrict__ out) {
    int b = blockIdx.x;
    if (g_flag[b] == 0) return;

    extern __shared__ unsigned char sm[];
    float4*        sbox = (float4*)(sm + K3_SBOX);
    float*         sar  = (float*)(sm + K3_SAR);
    unsigned char* sup  = sm + K3_SUP;

    int tid = threadIdx.x;
    float thr = thrp[0], sthr = sthrp[0];
    const float4* bb = boxes + (size_t)b * NB;
    for (int i = tid; i < NB; i += 1024) {
        float4 v = bb[i];
        sbox[i] = v;
        sar[i] = (v.z - v.x) * (v.w - v.y);
    }
    for (int idx = tid; idx < NC * NB; idx += 1024) {
        int c = idx >> 11, n = idx & (NB - 1);
        size_t g = (size_t)(b * NC + c) * NB + n;
        sup[idx] = (scores[g] > sthr) ? 0 : 1;
        out[g] = -1.0f;
    }
    __syncthreads();

    int warp = tid >> 5, lane = tid & 31;
    if (warp < NC) {
        int c = warp;
        volatile unsigned char* supc = sup + (c << 11);
        const float* spc = scores + (size_t)(b * NC + c) * NB;
        float*       opc = out + (size_t)(b * NC + c) * NB;
        for (;;) {
            // warp argmax over unsuppressed: score desc, tie idx asc.
            float bs = -1e30f; int bi = 1 << 30;
            for (int k = 0; k < NB / 32; k++) {
                int u = k * 32 + lane;
                if (!supc[u]) {
                    float s = spc[u];
                    if (s > bs || (s == bs && u < bi)) { bs = s; bi = u; }
                }
            }
            #pragma unroll
            for (int off = 16; off; off >>= 1) {
                float os = __shfl_down_sync(0xffffffffu, bs, off);
                int   oi = __shfl_down_sync(0xffffffffu, bi, off);
                if (os > bs || (os == bs && oi < bi)) { bs = os; bi = oi; }
            }
            bi = __shfl_sync(0xffffffffu, bi, 0);
            if (bi >= (1 << 30)) break;

            float4 tb = sbox[bi];
            float tar = sar[bi];
            float lf = (float)bi;
            for (int k = 0; k < NB / 32; k++) {
                int u = k * 32 + lane;
                if (!supc[u]) {
                    float4 ub = sbox[u];
                    float ix = fminf(tb.z, ub.z) - fmaxf(tb.x, ub.x);
                    float iy = fminf(tb.w, ub.w) - fmaxf(tb.y, ub.y);
                    ix = fmaxf(ix, 0.0f);
                    iy = fmaxf(iy, 0.0f);
                    float inter = ix * iy;
                    float unim  = fmaxf(tar + sar[u] - inter, 1e-6f);
                    if (inter > thr * unim) { supc[u] = 1; opc[u] = lf; }
                }
            }
            if (lane == 0) supc[bi] = 1;   // ensure progress even if thr >= 1
            __syncwarp();
        }
    }
}

// ---------------------------------------------------------------------------
extern "C" void kernel_launch(void* const* d_in, const int* in_sizes, int n_in,
                              void* d_out, int out_size) {
    const float4* boxes  = (const float4*)d_in[0];
    const float*  scores = (const float*)d_in[1];
    const float*  iouthr = (const float*)d_in[2];
    const float*  scothr = (const float*)d_in[3];
    float* out = (float*)d_out;

    cudaFuncSetAttribute(cc_kernel, cudaFuncAttributeMaxDynamicSharedMemorySize, K2_SMEM);
    cudaFuncSetAttribute(fb_kernel, cudaFuncAttributeMaxDynamicSharedMemorySize, K3_SMEM);

    adj_kernel<<<BATCH * 128, 512>>>(boxes, iouthr);
    cc_kernel<<<BATCH * 8, 256, K2_SMEM>>>(scores, scothr, out);
    fb_kernel<<<BATCH, 1024, K3_SMEM>>>(boxes, scores, iouthr, scothr, out);
}

// round 7
// speedup vs baseline: 4.8397x; 1.0141x over previous
#include <cuda_runtime.h>
#include <cuda_bf16.h>

#define BATCH  4
#define NB     2048
#define NC     4
#define ROWSL  16          // u16 slots per row: [0]=count, [1..15]=neighbors
#define MAXDEG 15
#define CAP    96          // max component size for per-thread greedy

// __device__ scratch (allocation-free rule). uint4 type => 32B-aligned rows.
__device__ uint4 g_adj_raw[(size_t)BATCH * NB * ROWSL / 8];
#define G_ADJ ((unsigned short*)g_adj_raw)
__device__ int g_flag[BATCH];

// ---------------------------------------------------------------------------
// K1: adjacency rows (count + list). 512 blocks x 512 thr, 16 rows/block.
// ---------------------------------------------------------------------------
__global__ void __launch_bounds__(512) adj_kernel(const float4* __restrict__ boxes,
                                                  const float* __restrict__ thrp) {
    __shared__ float4 sbox[NB];     // 32KB
    __shared__ float  sar[NB];      // 8KB
    int b    = blockIdx.x >> 7;
    int tile = blockIdx.x & 127;
    int tid  = threadIdx.x;
    if (blockIdx.x == 0 && tid < BATCH) g_flag[tid] = 0;

    const float4* bb = boxes + (size_t)b * NB;
    for (int i = tid; i < NB; i += 512) {
        float4 v = bb[i];
        sbox[i] = v;
        sar[i] = (v.z - v.x) * (v.w - v.y);
    }
    __syncthreads();

    float thr = thrp[0];
    int warp = tid >> 5, lane = tid & 31;
    int r = tile * 16 + warp;

    float4 rb = sbox[r];
    float rar = sar[r];
    int cnt = 0;
    unsigned short* row = G_ADJ + (size_t)(b * NB + r) * ROWSL;

    #pragma unroll 4
    for (int c = 0; c < NB / 32; c++) {
        int u = c * 32 + lane;
        float4 ub = sbox[u];
        float ix = fminf(rb.z, ub.z) - fmaxf(rb.x, ub.x);
        float iy = fminf(rb.w, ub.w) - fmaxf(rb.y, ub.y);
        ix = fmaxf(ix, 0.0f);
        iy = fmaxf(iy, 0.0f);
        float inter = ix * iy;
        float unim  = fmaxf(rar + sar[u] - inter, 1e-6f);
        bool hit = inter > thr * unim;               // == inter/max(uni,1e-6) > thr
        unsigned word = __ballot_sync(0xffffffffu, hit);
        if (c == (r >> 5)) word &= ~(1u << (r & 31));     // drop self
        if (lane == 0 && word) {
            int base = c * 32;
            while (word) {
                int j = __ffs(word) - 1;
                word &= word - 1u;
                if (cnt < MAXDEG) row[1 + cnt] = (unsigned short)(base + j);
                cnt++;                                // full count even if truncated
            }
        }
    }
    if (lane == 0) row[0] = (unsigned short)cnt;
}

// ---------------------------------------------------------------------------
// K2: per-thread component greedy. grid = BATCH*32, 64 thr, NO smem.
// Thread owns node i. Isolated -> write own outputs. Else BFS over fused
// count+list rows (1 LDG.128 per member typ.); linear-scan dedup on the tiny
// member list; only the component-min thread proceeds as root and writes ALL
// member outputs for all 4 classes. Disjoint components -> race-free.
// deg>MAXDEG or component>CAP -> g_flag[b] (exact fallback).
// Assumes thr < 1 (self-IoU = 1 > thr => active boxes self-match). Data: 0.5.
// ---------------------------------------------------------------------------
__device__ __forceinline__ int load_row(int b, int v, unsigned short* ent) {
    const uint4* rv = (const uint4*)(G_ADJ + (size_t)(b * NB + v) * ROWSL);
    uint4 w0 = rv[0];
    *(uint4*)ent = w0;                    // ent[0]=cnt, ent[1..7]=neighbors
    int cnt = ent[0];
    if (cnt > 7) *(uint4*)(ent + 8) = rv[1];
    return cnt;
}

__global__ void __launch_bounds__(64) cc_kernel(const float* __restrict__ scores,
                                                const float* __restrict__ sthrp,
                                                float* __restrict__ out) {
    int b = blockIdx.x >> 5;
    int i = (blockIdx.x & 31) * 64 + threadIdx.x;
    float sthr = sthrp[0];

    unsigned short ent[ROWSL];
    int d = load_row(b, i, ent);

    if (d == 0) {
        #pragma unroll
        for (int c = 0; c < NC; c++) {
            size_t g = (size_t)(b * NC + c) * NB + i;
            out[g] = (scores[g] > sthr) ? (float)i : -1.0f;
        }
        return;
    }
    if (d > MAXDEG) { g_flag[b] = 1; return; }

    // BFS with linear-scan dedup (components are tiny).
    unsigned short memb[CAP];
    memb[0] = (unsigned short)i;
    int mc = 1;
    bool root = true, ovf = false;

    for (int h = 0; h < mc; h++) {
        int dv = (h == 0) ? d : load_row(b, memb[h], ent);
        if (dv > MAXDEG) { ovf = true; break; }
        for (int e = 1; e <= dv; e++) {
            int u = ent[e];
            if (u < i) { root = false; break; }       // not the component min
            bool seen = false;
            for (int j = 0; j < mc; j++) if (memb[j] == u) { seen = true; break; }
            if (!seen) {
                if (mc == CAP) { ovf = true; break; }
                memb[mc++] = (unsigned short)u;
            }
        }
        if (!root || ovf) break;
    }
    if (ovf) { g_flag[b] = 1; return; }
    if (!root) return;

    // Exact greedy per class, fully local (max score, tie -> min index).
    float sc[CAP];
    for (int c = 0; c < NC; c++) {
        const float* spc = scores + (size_t)(b * NC + c) * NB;
        float*       opc = out + (size_t)(b * NC + c) * NB;
        unsigned act[3] = {0u, 0u, 0u};               // unclaimed-active members
        int nact = 0;
        for (int j = 0; j < mc; j++) {
            float s = spc[memb[j]];
            sc[j] = s;
            if (s > sthr) { act[j >> 5] |= 1u << (j & 31); nact++; }
            else opc[memb[j]] = -1.0f;
        }
        while (nact > 0) {
            int bj = -1, bidx = 1 << 30;
            float bs = -1e30f;
            for (int j = 0; j < mc; j++) {
                if ((act[j >> 5] >> (j & 31)) & 1u) {
                    float s = sc[j];
                    int g = memb[j];
                    if (s > bs || (s == bs && g < bidx)) { bs = s; bj = j; bidx = g; }
                }
            }
            act[bj >> 5] &= ~(1u << (bj & 31));
            nact--;
            opc[bidx] = (float)bidx;                   // self-claim (thr < 1)
            int dv = load_row(b, bidx, ent);           // L1-hot after BFS
            for (int e = 1; e <= dv; e++) {
                int u = ent[e];
                for (int j = 0; j < mc; j++) {         // slot lookup (mc small)
                    if (memb[j] == u) {
                        if ((act[j >> 5] >> (j & 31)) & 1u) {
                            act[j >> 5] &= ~(1u << (j & 31));
                            nact--;
                            opc[u] = (float)bidx;
                        }
                        break;
                    }
                }
            }
        }
    }
}

// ---------------------------------------------------------------------------
// K3: exact serial fallback per batch; early-exits unless g_flag[b] set.
// ---------------------------------------------------------------------------
#define K3_SBOX 0                       // 2048 float4
#define K3_SAR  32768                   // 2048 float
#define K3_SUP  40960                   // NC*2048 u8
#define K3_SMEM (K3_SUP + NC * NB)

__global__ void __launch_bounds__(1024) fb_kernel(const float4* __restrict__ boxes,
                                                  const float* __restrict__ scores,
                                                  const float* __restrict__ thrp,
                                                  const float* __restrict__ sthrp,
                                                  float* __restrict__ out) {
    int b = blockIdx.x;
    if (g_flag[b] == 0) return;

    extern __shared__ unsigned char sm[];
    float4*        sbox = (float4*)(sm + K3_SBOX);
    float*         sar  = (float*)(sm + K3_SAR);
    unsigned char* sup  = sm + K3_SUP;

    int tid = threadIdx.x;
    float thr = thrp[0], sthr = sthrp[0];
    const float4* bb = boxes + (size_t)b * NB;
    for (int i = tid; i < NB; i += 1024) {
        float4 v = bb[i];
        sbox[i] = v;
        sar[i] = (v.z - v.x) * (v.w - v.y);
    }
    for (int idx = tid; idx < NC * NB; idx += 1024) {
        int c = idx >> 11, n = idx & (NB - 1);
        size_t g = (size_t)(b * NC + c) * NB + n;
        sup[idx] = (scores[g] > sthr) ? 0 : 1;
        out[g] = -1.0f;
    }
    __syncthreads();

    int warp = tid >> 5, lane = tid & 31;
    if (warp < NC) {
        int c = warp;
        volatile unsigned char* supc = sup + (c << 11);
        const float* spc = scores + (size_t)(b * NC + c) * NB;
        float*       opc = out + (size_t)(b * NC + c) * NB;
        for (;;) {
            // warp argmax over unsuppressed: score desc, tie idx asc.
            float bs = -1e30f; int bi = 1 << 30;
            for (int k = 0; k < NB / 32; k++) {
                int u = k * 32 + lane;
                if (!supc[u]) {
                    float s = spc[u];
                    if (s > bs || (s == bs && u < bi)) { bs = s; bi = u; }
                }
            }
            #pragma unroll
            for (int off = 16; off; off >>= 1) {
                float os = __shfl_down_sync(0xffffffffu, bs, off);
                int   oi = __shfl_down_sync(0xffffffffu, bi, off);
                if (os > bs || (os == bs && oi < bi)) { bs = os; bi = oi; }
            }
            bi = __shfl_sync(0xffffffffu, bi, 0);
            if (bi >= (1 << 30)) break;

            float4 tb = sbox[bi];
            float tar = sar[bi];
            float lf = (float)bi;
            for (int k = 0; k < NB / 32; k++) {
                int u = k * 32 + lane;
                if (!supc[u]) {
                    float4 ub = sbox[u];
                    float ix = fminf(tb.z, ub.z) - fmaxf(tb.x, ub.x);
                    float iy = fminf(tb.w, ub.w) - fmaxf(tb.y, ub.y);
                    ix = fmaxf(ix, 0.0f);
                    iy = fmaxf(iy, 0.0f);
                    float inter = ix * iy;
                    float unim  = fmaxf(tar + sar[u] - inter, 1e-6f);
                    if (inter > thr * unim) { supc[u] = 1; opc[u] = lf; }
                }
            }
            if (lane == 0) supc[bi] = 1;   // ensure progress even if thr >= 1
            __syncwarp();
        }
    }
}

// ---------------------------------------------------------------------------
extern "C" void kernel_launch(void* const* d_in, const int* in_sizes, int n_in,
                              void* d_out, int out_size) {
    const float4* boxes  = (const float4*)d_in[0];
    const float*  scores = (const float*)d_in[1];
    const float*  iouthr = (const float*)d_in[2];
    const float*  scothr = (const float*)d_in[3];
    float* out = (float*)d_out;

    cudaFuncSetAttribute(fb_kernel, cudaFuncAttributeMaxDynamicSharedMemorySize, K3_SMEM);

    adj_kernel<<<BATCH * 128, 512>>>(boxes, iouthr);
    cc_kernel<<<BATCH * 32, 64>>>(scores, scothr, out);
    fb_kernel<<<BATCH, 1024, K3_SMEM>>>(boxes, scores, iouthr, scothr, out);
}